// round 1
// baseline (speedup 1.0000x reference)
#include <cuda_runtime.h>
#include <cuda_bf16.h>
#include <math.h>

// ---------------------------------------------------------------------------
// Problem constants (fixed by the reference setup)
// ---------------------------------------------------------------------------
#define BATCH     2
#define NQ        10000
#define MTOT      21760          // 128^2 + 64^2 + 32^2 + 16^2
#define EMBED     256
#define HEADS     8
#define HEAD_DIM  32
#define LEVELS    4
#define POINTS    4

// level spatial sizes (square) and start offsets
__device__ __constant__ int c_shape[LEVELS]  = {128, 64, 32, 16};
__device__ __constant__ int c_start[LEVELS]  = {0, 16384, 20480, 21504};

// ---------------------------------------------------------------------------
// Device scratch (static allocation is the sanctioned workaround)
// ---------------------------------------------------------------------------
__device__ float g_v[BATCH * MTOT * EMBED];        // projected value  (44.6 MB)
__device__ float g_off[BATCH * NQ * (HEADS*LEVELS*POINTS*2)]; // offsets (20.5 MB)
__device__ float g_attn[BATCH * NQ * (HEADS*LEVELS*POINTS)];  // logits  (10.2 MB)

// ---------------------------------------------------------------------------
// SGEMM:  C[M,Nn] = A[M,K] * B[K,Nn] + bias[Nn]
// BM=128, BN=64, BK=16, microtile 8x4, 256 threads.
// Requires: Nn % 64 == 0, K % 16 == 0, pointers 16B aligned. M arbitrary.
// ---------------------------------------------------------------------------
#define GBM 128
#define GBN 64
#define GBK 16
#define GTM 8
#define GTN 4

__global__ __launch_bounds__(256) void sgemm_bias(
    const float* __restrict__ A, const float* __restrict__ Bw,
    const float* __restrict__ bias, float* __restrict__ C,
    int M, int Nn, int K)
{
    __shared__ float As[GBK][GBM];
    __shared__ float Bs[GBK][GBN];

    const int block_row = blockIdx.y * GBM;
    const int block_col = blockIdx.x * GBN;
    const int tid  = threadIdx.x;
    const int tcol = tid & 15;   // 0..15  (BN/TN)
    const int trow = tid >> 4;   // 0..15  (BM/TM)

    float acc[GTM][GTN];
#pragma unroll
    for (int i = 0; i < GTM; i++)
#pragma unroll
        for (int j = 0; j < GTN; j++) acc[i][j] = 0.0f;

    // A tile: 128x16 floats = 512 float4, 2 per thread
    // B tile: 16x64  floats = 256 float4, 1 per thread
    const int b_row  = tid >> 4;        // 0..15
    const int b_col4 = (tid & 15) * 4;  // 0..60

    for (int k0 = 0; k0 < K; k0 += GBK) {
        // load A (transposed into As[k][m])
#pragma unroll
        for (int li = 0; li < 2; li++) {
            int e     = tid + li * 256;       // 0..511
            int a_row = e >> 2;               // 0..127
            int a_c4  = (e & 3) * 4;          // 0,4,8,12
            float4 av = make_float4(0.f, 0.f, 0.f, 0.f);
            int gr = block_row + a_row;
            if (gr < M)
                av = *(const float4*)&A[(size_t)gr * K + k0 + a_c4];
            As[a_c4 + 0][a_row] = av.x;
            As[a_c4 + 1][a_row] = av.y;
            As[a_c4 + 2][a_row] = av.z;
            As[a_c4 + 3][a_row] = av.w;
        }
        // load B
        {
            float4 bv = *(const float4*)&Bw[(size_t)(k0 + b_row) * Nn + block_col + b_col4];
            *(float4*)&Bs[b_row][b_col4] = bv;
        }
        __syncthreads();

#pragma unroll
        for (int k = 0; k < GBK; k++) {
            float4 a0 = *(const float4*)&As[k][trow * GTM + 0];
            float4 a1 = *(const float4*)&As[k][trow * GTM + 4];
            float4 bq = *(const float4*)&Bs[k][tcol * GTN];
            float ar[GTM] = {a0.x, a0.y, a0.z, a0.w, a1.x, a1.y, a1.z, a1.w};
            float br[GTN] = {bq.x, bq.y, bq.z, bq.w};
#pragma unroll
            for (int i = 0; i < GTM; i++)
#pragma unroll
                for (int j = 0; j < GTN; j++)
                    acc[i][j] = fmaf(ar[i], br[j], acc[i][j]);
        }
        __syncthreads();
    }

#pragma unroll
    for (int i = 0; i < GTM; i++) {
        int gr = block_row + trow * GTM + i;
        if (gr >= M) continue;
#pragma unroll
        for (int j = 0; j < GTN; j++) {
            int gc = block_col + tcol * GTN + j;
            C[(size_t)gr * Nn + gc] = acc[i][j] + bias[gc];
        }
    }
}

// ---------------------------------------------------------------------------
// Fused softmax + bilinear sampling + weighted accumulation.
// One block per (b, n); one warp per head; one lane per channel-in-head.
// ---------------------------------------------------------------------------
__global__ __launch_bounds__(256) void deform_sample(
    const float* __restrict__ ref_points,   // [B, N, 1, 2]
    float* __restrict__ out)                // [B, N, EMBED]
{
    const int bn   = blockIdx.x;            // 0 .. B*N-1
    const int b    = bn / NQ;
    const int head = threadIdx.x >> 5;
    const int lane = threadIdx.x & 31;

    const float rx = ref_points[bn * 2 + 0];
    const float ry = ref_points[bn * 2 + 1];

    const float* off = g_off  + (size_t)bn * (HEADS*LEVELS*POINTS*2) + head * (LEVELS*POINTS*2);
    const float* lg  = g_attn + (size_t)bn * (HEADS*LEVELS*POINTS)   + head * (LEVELS*POINTS);

    // softmax over the 16 (level,point) logits — redundant per lane, trivial cost
    float lw[LEVELS*POINTS];
#pragma unroll
    for (int i = 0; i < LEVELS*POINTS; i++) lw[i] = lg[i];
    float mx = lw[0];
#pragma unroll
    for (int i = 1; i < LEVELS*POINTS; i++) mx = fmaxf(mx, lw[i]);
    float sum = 0.f;
#pragma unroll
    for (int i = 0; i < LEVELS*POINTS; i++) { lw[i] = expf(lw[i] - mx); sum += lw[i]; }
    const float inv = 1.0f / sum;

    float acc = 0.0f;

#pragma unroll
    for (int lv = 0; lv < LEVELS; lv++) {
        const int S  = c_shape[lv];           // Hl == Wl
        const float fS = (float)S;
        const float* vb = g_v + ((size_t)(b * MTOT + c_start[lv])) * EMBED
                              + head * HEAD_DIM + lane;
#pragma unroll
        for (int p = 0; p < POINTS; p++) {
            const float ox = off[(lv * POINTS + p) * 2 + 0];
            const float oy = off[(lv * POINTS + p) * 2 + 1];
            // match reference:  x = (rx + ox/W) * W - 0.5
            const float x = (rx + ox / fS) * fS - 0.5f;
            const float y = (ry + oy / fS) * fS - 0.5f;
            const float x0f = floorf(x), y0f = floorf(y);
            const float lx = x - x0f,  ly = y - y0f;
            const int x0 = (int)x0f, y0 = (int)y0f;

            const float w00 = (1.f - lx) * (1.f - ly);
            const float w01 = lx * (1.f - ly);
            const float w10 = (1.f - lx) * ly;
            const float w11 = lx * ly;

            float samp = 0.f;
            const bool vx0 = (x0 >= 0) & (x0 < S);
            const bool vx1 = (x0 + 1 >= 0) & (x0 + 1 < S);
            if (y0 >= 0 && y0 < S) {
                const size_t rb = (size_t)(y0 * S) * EMBED;
                if (vx0) samp = fmaf(w00, vb[rb + (size_t)x0 * EMBED], samp);
                if (vx1) samp = fmaf(w01, vb[rb + (size_t)(x0 + 1) * EMBED], samp);
            }
            if (y0 + 1 >= 0 && y0 + 1 < S) {
                const size_t rb = (size_t)((y0 + 1) * S) * EMBED;
                if (vx0) samp = fmaf(w10, vb[rb + (size_t)x0 * EMBED], samp);
                if (vx1) samp = fmaf(w11, vb[rb + (size_t)(x0 + 1) * EMBED], samp);
            }
            acc = fmaf(lw[lv * POINTS + p] * inv, samp, acc);
        }
    }

    out[(size_t)bn * EMBED + head * HEAD_DIM + lane] = acc;
}

// ---------------------------------------------------------------------------
// Launch
// ---------------------------------------------------------------------------
extern "C" void kernel_launch(void* const* d_in, const int* in_sizes, int n_in,
                              void* d_out, int out_size)
{
    const float* query  = (const float*)d_in[0];
    // d_in[1] = key (unused by reference)
    const float* value  = (const float*)d_in[2];
    const float* refpts = (const float*)d_in[3];
    // d_in[4] = spatial_shapes, d_in[5] = level_start_idx (compile-time constants)
    const float* W_off  = (const float*)d_in[6];
    const float* b_off  = (const float*)d_in[7];
    const float* W_attn = (const float*)d_in[8];
    const float* b_attn = (const float*)d_in[9];
    const float* W_v    = (const float*)d_in[10];
    const float* b_v    = (const float*)d_in[11];
    float* out = (float*)d_out;

    void *pv, *poff, *pattn;
    cudaGetSymbolAddress(&pv,   g_v);
    cudaGetSymbolAddress(&poff, g_off);
    cudaGetSymbolAddress(&pattn, g_attn);

    const int MV = BATCH * MTOT;   // 43520
    const int MQ = BATCH * NQ;     // 20000

    // 1) v = value @ W_v + b_v            [43520,256] x [256,256]
    {
        dim3 grid(EMBED / GBN, (MV + GBM - 1) / GBM);
        sgemm_bias<<<grid, 256>>>(value, W_v, b_v, (float*)pv, MV, EMBED, EMBED);
    }
    // 2) off = query @ W_off + b_off      [20000,256] x [256,256]
    {
        dim3 grid(256 / GBN, (MQ + GBM - 1) / GBM);
        sgemm_bias<<<grid, 256>>>(query, W_off, b_off, (float*)poff, MQ, 256, EMBED);
    }
    // 3) attn = query @ W_attn + b_attn   [20000,256] x [256,128]
    {
        dim3 grid(128 / GBN, (MQ + GBM - 1) / GBM);
        sgemm_bias<<<grid, 256>>>(query, W_attn, b_attn, (float*)pattn, MQ, 128, EMBED);
    }
    // 4) fused softmax + sampling
    deform_sample<<<BATCH * NQ, 256>>>(refpts, out);
}

// round 3
// speedup vs baseline: 1.5247x; 1.5247x over previous
#include <cuda_runtime.h>
#include <cuda_bf16.h>
#include <math.h>

// ---------------------------------------------------------------------------
// Problem constants (fixed by the reference setup)
// ---------------------------------------------------------------------------
#define BATCH     2
#define NQ        10000
#define MTOT      21760          // 128^2 + 64^2 + 32^2 + 16^2
#define EMBED     256
#define HEADS     8
#define HEAD_DIM  32
#define LEVELS    4
#define POINTS    4
#define COMBOS    (HEADS*LEVELS*POINTS)   // 128 per query

__device__ __constant__ int c_shape[LEVELS]  = {128, 64, 32, 16};
__device__ __constant__ int c_start[LEVELS]  = {0, 16384, 20480, 21504};

// ---------------------------------------------------------------------------
// Device scratch
// ---------------------------------------------------------------------------
__device__ float g_v[BATCH * MTOT * EMBED];                    // projected value
__device__ float g_off[BATCH * NQ * (COMBOS*2)];               // offsets
__device__ float g_attn[BATCH * NQ * COMBOS];                  // logits

// ---------------------------------------------------------------------------
// SGEMM:  C[M,Nn] = A[M,K] * B[K,Nn] + bias[Nn]   (at FFMA roofline)
// ---------------------------------------------------------------------------
#define GBM 128
#define GBN 64
#define GBK 16
#define GTM 8
#define GTN 4

__global__ __launch_bounds__(256) void sgemm_bias(
    const float* __restrict__ A, const float* __restrict__ Bw,
    const float* __restrict__ bias, float* __restrict__ C,
    int M, int Nn, int K)
{
    __shared__ float As[GBK][GBM];
    __shared__ float Bs[GBK][GBN];

    const int block_row = blockIdx.y * GBM;
    const int block_col = blockIdx.x * GBN;
    const int tid  = threadIdx.x;
    const int tcol = tid & 15;
    const int trow = tid >> 4;

    float acc[GTM][GTN];
#pragma unroll
    for (int i = 0; i < GTM; i++)
#pragma unroll
        for (int j = 0; j < GTN; j++) acc[i][j] = 0.0f;

    const int b_row  = tid >> 4;
    const int b_col4 = (tid & 15) * 4;

    for (int k0 = 0; k0 < K; k0 += GBK) {
#pragma unroll
        for (int li = 0; li < 2; li++) {
            int e     = tid + li * 256;
            int a_row = e >> 2;
            int a_c4  = (e & 3) * 4;
            float4 av = make_float4(0.f, 0.f, 0.f, 0.f);
            int gr = block_row + a_row;
            if (gr < M)
                av = *(const float4*)&A[(size_t)gr * K + k0 + a_c4];
            As[a_c4 + 0][a_row] = av.x;
            As[a_c4 + 1][a_row] = av.y;
            As[a_c4 + 2][a_row] = av.z;
            As[a_c4 + 3][a_row] = av.w;
        }
        {
            float4 bv = *(const float4*)&Bw[(size_t)(k0 + b_row) * Nn + block_col + b_col4];
            *(float4*)&Bs[b_row][b_col4] = bv;
        }
        __syncthreads();

#pragma unroll
        for (int k = 0; k < GBK; k++) {
            float4 a0 = *(const float4*)&As[k][trow * GTM + 0];
            float4 a1 = *(const float4*)&As[k][trow * GTM + 4];
            float4 bq = *(const float4*)&Bs[k][tcol * GTN];
            float ar[GTM] = {a0.x, a0.y, a0.z, a0.w, a1.x, a1.y, a1.z, a1.w};
            float br[GTN] = {bq.x, bq.y, bq.z, bq.w};
#pragma unroll
            for (int i = 0; i < GTM; i++)
#pragma unroll
                for (int j = 0; j < GTN; j++)
                    acc[i][j] = fmaf(ar[i], br[j], acc[i][j]);
        }
        __syncthreads();
    }

#pragma unroll
    for (int i = 0; i < GTM; i++) {
        int gr = block_row + trow * GTM + i;
        if (gr >= M) continue;
#pragma unroll
        for (int j = 0; j < GTN; j++) {
            int gc = block_col + tcol * GTN + j;
            C[(size_t)gr * Nn + gc] = acc[i][j] + bias[gc];
        }
    }
}

// ---------------------------------------------------------------------------
// Sampler v2 (fixed): two-phase.
//   Phase 1: thread = one (q,head,lv,p) combo: shuffle-softmax (16-lane
//            groups), bilinear weights (validity & attn weight folded),
//            clamped flat indices -> smem.
//   Phase 2: warp = head, lane = channel; pure gather + FFMA.
// ---------------------------------------------------------------------------
#define QPB 2

__global__ __launch_bounds__(256) void deform_sample(
    const float* __restrict__ ref_points,   // [B, N, 1, 2]
    float* __restrict__ out)                // [B, N, EMBED]
{
    __shared__ float4 s_w[QPB * COMBOS];
    __shared__ int4   s_i[QPB * COMBOS];

    const int t = threadIdx.x;

    // ---------------- Phase 1 ----------------
    {
        const int q    = t >> 7;
        const int c    = t & 127;
        const int head = c >> 4;
        const int i16  = c & 15;
        const int lv   = i16 >> 2;
        const int bn   = blockIdx.x * QPB + q;
        const int b    = bn / NQ;

        // 16-wide shuffle softmax (butterfly on the ACCUMULATOR)
        float lg = g_attn[(size_t)bn * COMBOS + c];
        float mx = lg;
#pragma unroll
        for (int s = 8; s >= 1; s >>= 1)
            mx = fmaxf(mx, __shfl_xor_sync(0xffffffffu, mx, s));
        float e = __expf(lg - mx);
        float ssum = e;
#pragma unroll
        for (int s = 8; s >= 1; s >>= 1)
            ssum += __shfl_xor_sync(0xffffffffu, ssum, s);   // FIX: shuffle ssum
        const float aw = e / ssum;

        const float2 od = ((const float2*)g_off)[(size_t)bn * COMBOS + c];
        const float rx = ref_points[bn * 2 + 0];
        const float ry = ref_points[bn * 2 + 1];

        const int   S  = c_shape[lv];
        const float fS = (float)S;

        const float x = (rx + od.x / fS) * fS - 0.5f;
        const float y = (ry + od.y / fS) * fS - 0.5f;
        const float x0f = floorf(x), y0f = floorf(y);
        const float lx = x - x0f, ly = y - y0f;
        const int x0 = (int)x0f, y0 = (int)y0f;
        const int x1 = x0 + 1,   y1 = y0 + 1;

        const bool vx0 = ((unsigned)x0 < (unsigned)S);
        const bool vx1 = ((unsigned)x1 < (unsigned)S);
        const bool vy0 = ((unsigned)y0 < (unsigned)S);
        const bool vy1 = ((unsigned)y1 < (unsigned)S);

        const int xc0 = min(max(x0, 0), S - 1);
        const int xc1 = min(max(x1, 0), S - 1);
        const int yc0 = min(max(y0, 0), S - 1);
        const int yc1 = min(max(y1, 0), S - 1);

        float4 wv;
        wv.x = (vx0 && vy0) ? (1.f - lx) * (1.f - ly) * aw : 0.f;
        wv.y = (vx1 && vy0) ? lx * (1.f - ly) * aw : 0.f;
        wv.z = (vx0 && vy1) ? (1.f - lx) * ly * aw : 0.f;
        wv.w = (vx1 && vy1) ? lx * ly * aw : 0.f;

        const int base = b * MTOT + c_start[lv];
        const int hoff = head * HEAD_DIM;
        int4 iv;
        iv.x = (base + yc0 * S + xc0) * EMBED + hoff;
        iv.y = (base + yc0 * S + xc1) * EMBED + hoff;
        iv.z = (base + yc1 * S + xc0) * EMBED + hoff;
        iv.w = (base + yc1 * S + xc1) * EMBED + hoff;

        s_w[t] = wv;
        s_i[t] = iv;
    }
    __syncthreads();

    // ---------------- Phase 2 ----------------
    const int head = t >> 5;
    const int lane = t & 31;

#pragma unroll
    for (int q = 0; q < QPB; q++) {
        const int bn   = blockIdx.x * QPB + q;
        const int slot = q * COMBOS + head * (LEVELS * POINTS);

        float acc = 0.0f;
#pragma unroll
        for (int i = 0; i < LEVELS * POINTS; i++) {
            const float4 wv = s_w[slot + i];
            const int4   iv = s_i[slot + i];
            float v0 = __ldg(&g_v[iv.x + lane]);
            float v1 = __ldg(&g_v[iv.y + lane]);
            float v2 = __ldg(&g_v[iv.z + lane]);
            float v3 = __ldg(&g_v[iv.w + lane]);
            acc = fmaf(wv.x, v0, acc);
            acc = fmaf(wv.y, v1, acc);
            acc = fmaf(wv.z, v2, acc);
            acc = fmaf(wv.w, v3, acc);
        }
        out[(size_t)bn * EMBED + head * HEAD_DIM + lane] = acc;
    }
}

// ---------------------------------------------------------------------------
// Launch
// ---------------------------------------------------------------------------
extern "C" void kernel_launch(void* const* d_in, const int* in_sizes, int n_in,
                              void* d_out, int out_size)
{
    const float* query  = (const float*)d_in[0];
    const float* value  = (const float*)d_in[2];
    const float* refpts = (const float*)d_in[3];
    const float* W_off  = (const float*)d_in[6];
    const float* b_off  = (const float*)d_in[7];
    const float* W_attn = (const float*)d_in[8];
    const float* b_attn = (const float*)d_in[9];
    const float* W_v    = (const float*)d_in[10];
    const float* b_v    = (const float*)d_in[11];
    float* out = (float*)d_out;

    void *pv, *poff, *pattn;
    cudaGetSymbolAddress(&pv,   g_v);
    cudaGetSymbolAddress(&poff, g_off);
    cudaGetSymbolAddress(&pattn, g_attn);

    const int MV = BATCH * MTOT;   // 43520
    const int MQ = BATCH * NQ;     // 20000

    // 1) v = value @ W_v + b_v
    {
        dim3 grid(EMBED / GBN, (MV + GBM - 1) / GBM);
        sgemm_bias<<<grid, 256>>>(value, W_v, b_v, (float*)pv, MV, EMBED, EMBED);
    }
    // 2) off = query @ W_off + b_off
    {
        dim3 grid(256 / GBN, (MQ + GBM - 1) / GBM);
        sgemm_bias<<<grid, 256>>>(query, W_off, b_off, (float*)poff, MQ, 256, EMBED);
    }
    // 3) attn = query @ W_attn + b_attn
    {
        dim3 grid(128 / GBN, (MQ + GBM - 1) / GBM);
        sgemm_bias<<<grid, 256>>>(query, W_attn, b_attn, (float*)pattn, MQ, 128, EMBED);
    }
    // 4) fused softmax + sampling (2 queries per block)
    deform_sample<<<(BATCH * NQ) / QPB, 256>>>(refpts, out);
}

// round 6
// speedup vs baseline: 2.0791x; 1.3636x over previous
#include <cuda_runtime.h>
#include <cuda_bf16.h>
#include <math.h>
#include <stdint.h>

// ---------------------------------------------------------------------------
// Problem constants
// ---------------------------------------------------------------------------
#define BATCH     2
#define NQ        10000
#define MTOT      21760
#define EMBED     256
#define HEADS     8
#define HEAD_DIM  32
#define LEVELS    4
#define POINTS    4
#define COMBOS    (HEADS*LEVELS*POINTS)
#define KDIM      256

__device__ __constant__ int c_shape[LEVELS]  = {128, 64, 32, 16};
__device__ __constant__ int c_start[LEVELS]  = {0, 16384, 20480, 21504};

// ---------------------------------------------------------------------------
// Device scratch
// ---------------------------------------------------------------------------
__device__ float g_v[BATCH * MTOT * EMBED];
__device__ float g_off[BATCH * NQ * (COMBOS*2)];
__device__ float g_attn[BATCH * NQ * COMBOS];

__device__ __nv_bfloat16 g_val_hi[BATCH * MTOT * KDIM];
__device__ __nv_bfloat16 g_val_lo[BATCH * MTOT * KDIM];
__device__ __nv_bfloat16 g_q_hi[BATCH * NQ * KDIM];
__device__ __nv_bfloat16 g_q_lo[BATCH * NQ * KDIM];
__device__ __nv_bfloat16 g_wv_hi[256 * KDIM],  g_wv_lo[256 * KDIM];
__device__ __nv_bfloat16 g_wo_hi[256 * KDIM],  g_wo_lo[256 * KDIM];
__device__ __nv_bfloat16 g_wa_hi[128 * KDIM],  g_wa_lo[128 * KDIM];

// ---------------------------------------------------------------------------
// PTX wrappers (baseline sm_80+ features only — no 'a'-suffix target needed)
// ---------------------------------------------------------------------------
__device__ __forceinline__ uint32_t smem_u32(const void* p) {
    uint32_t a;
    asm("{ .reg .u64 t; cvta.to.shared.u64 t, %1; cvt.u32.u64 %0, t; }" : "=r"(a) : "l"(p));
    return a;
}
__device__ __forceinline__ void ldsm4(uint32_t* r, uint32_t addr) {
    asm volatile("ldmatrix.sync.aligned.m8n8.x4.shared.b16 {%0,%1,%2,%3}, [%4];"
        : "=r"(r[0]), "=r"(r[1]), "=r"(r[2]), "=r"(r[3]) : "r"(addr));
}
__device__ __forceinline__ void mma_bf16(float* c, const uint32_t* a, const uint32_t* b) {
    asm volatile("mma.sync.aligned.m16n8k16.row.col.f32.bf16.bf16.f32 "
        "{%0,%1,%2,%3}, {%4,%5,%6,%7}, {%8,%9}, {%0,%1,%2,%3};"
        : "+f"(c[0]), "+f"(c[1]), "+f"(c[2]), "+f"(c[3])
        : "r"(a[0]), "r"(a[1]), "r"(a[2]), "r"(a[3]), "r"(b[0]), "r"(b[1]));
}

// ---------------------------------------------------------------------------
// Prep kernels: fp32 -> bf16 hi/lo split (and weight transpose)
// ---------------------------------------------------------------------------
__global__ void split_rows(const float* __restrict__ in,
                           __nv_bfloat16* __restrict__ hi,
                           __nv_bfloat16* __restrict__ lo, int n4)
{
    int i = blockIdx.x * blockDim.x + threadIdx.x;
    if (i >= n4) return;
    float4 a = ((const float4*)in)[i];
    __nv_bfloat16 h[4], l[4];
    float v[4] = {a.x, a.y, a.z, a.w};
#pragma unroll
    for (int j = 0; j < 4; j++) {
        h[j] = __float2bfloat16(v[j]);
        l[j] = __float2bfloat16(v[j] - __bfloat162float(h[j]));
    }
    ((uint2*)hi)[i] = *(uint2*)h;
    ((uint2*)lo)[i] = *(uint2*)l;
}

__global__ void transpose_split(const float* __restrict__ W,
                                __nv_bfloat16* __restrict__ hi,
                                __nv_bfloat16* __restrict__ lo, int Nin)
{
    int idx = blockIdx.x * blockDim.x + threadIdx.x;
    if (idx >= Nin * KDIM) return;
    int n = idx >> 8;
    int k = idx & 255;
    float v = W[k * Nin + n];
    __nv_bfloat16 h = __float2bfloat16(v);
    hi[idx] = h;
    lo[idx] = __float2bfloat16(v - __bfloat162float(h));
}

// ---------------------------------------------------------------------------
// HMMA GEMM:  C[M,N] = A[M,256] * Bt[N,256]^T + bias
// CTA: 256 thr (8 warps, 2m x 4n). Tile M=128, N=64, full K=256 in smem.
// bf16 hi/lo 3-term split. Swizzled smem, conflict-free ldmatrix.
// ---------------------------------------------------------------------------
#define SA_HI 0
#define SA_LO 65536
#define SB_HI 131072
#define SB_LO 163840
#define SM_TOTAL 196608

// smem offset for (row, 16B-chunk) in a 512B-row tile, XOR-swizzled
__device__ __forceinline__ uint32_t sw_off(int row, int ch) {
    return (uint32_t)row * 512u + (uint32_t)((ch ^ (row & 7)) << 4);
}

__global__ __launch_bounds__(256) void gemm_hmma(
    const __nv_bfloat16* __restrict__ Ahi, const __nv_bfloat16* __restrict__ Alo,
    const __nv_bfloat16* __restrict__ Bhi, const __nv_bfloat16* __restrict__ Blo,
    const float* __restrict__ bias, float* __restrict__ C, int M, int N)
{
    extern __shared__ char smem[];
    const uint32_t sb = smem_u32(smem);
    const int tid  = threadIdx.x;
    const int wid  = tid >> 5;
    const int lane = tid & 31;
    const int wm   = wid & 1;       // 0..1  (m: 64 rows each)
    const int wn   = wid >> 1;      // 0..3  (n: 16 cols each)
    const int row0 = blockIdx.y * 128;
    const int col0 = blockIdx.x * 64;

    // ---- stage A (128x256 bf16 hi+lo) ----
#pragma unroll
    for (int i = 0; i < 16; i++) {
        int c   = tid + i * 256;         // 0..4095
        int row = c >> 5;
        int ch  = c & 31;
        int gr  = row0 + row;
        uint32_t off = sw_off(row, ch);
        uint4 vh = make_uint4(0,0,0,0), vl = make_uint4(0,0,0,0);
        if (gr < M) {
            size_t gi = (size_t)gr * 32 + ch;
            vh = ((const uint4*)Ahi)[gi];
            vl = ((const uint4*)Alo)[gi];
        }
        *(uint4*)(smem + SA_HI + off) = vh;
        *(uint4*)(smem + SA_LO + off) = vl;
    }
    // ---- stage B (64x256 bf16 hi+lo) ----
#pragma unroll
    for (int i = 0; i < 8; i++) {
        int c   = tid + i * 256;         // 0..2047
        int row = c >> 5;
        int ch  = c & 31;
        uint32_t off = sw_off(row, ch);
        size_t gi = (size_t)(col0 + row) * 32 + ch;
        *(uint4*)(smem + SB_HI + off) = ((const uint4*)Bhi)[gi];
        *(uint4*)(smem + SB_LO + off) = ((const uint4*)Blo)[gi];
    }
    __syncthreads();

    // ---- fragment addressing ----
    // A ldmatrix.x4 (per m16 tile): row = base + (lane&15), chunk += lane>>4
    int rA[4], xA[4];
    const int cAdd = lane >> 4;
#pragma unroll
    for (int tm = 0; tm < 4; tm++) {
        rA[tm] = wm * 64 + tm * 16 + (lane & 15);
        xA[tm] = rA[tm] & 7;
    }
    // B ldmatrix.x4 (2 n8 tiles): row = wn*16 + ((lane>>4)&1)*8 + (lane&7)
    const int rB   = wn * 16 + ((lane >> 4) & 1) * 8 + (lane & 7);
    const int xB   = rB & 7;
    const int cBdd = (lane >> 3) & 1;

    float acc[4][2][4];
#pragma unroll
    for (int tm = 0; tm < 4; tm++)
#pragma unroll
        for (int tn = 0; tn < 2; tn++)
#pragma unroll
            for (int f = 0; f < 4; f++) acc[tm][tn][f] = 0.f;

    // ---- main loop: 16 k-steps; per step 10 ldmatrix.x4 + 24 HMMA ----
#pragma unroll
    for (int ks = 0; ks < 16; ks++) {
        const int k0c = 2 * ks;
        uint32_t bh[4], bl[4];
        {
            uint32_t ba = sb + (uint32_t)rB * 512u
                        + (uint32_t)(((k0c + cBdd) ^ xB) << 4);
            ldsm4(bh, ba + SB_HI);
            ldsm4(bl, ba + SB_LO);
        }
        uint32_t ah[4][4], al[4][4];
#pragma unroll
        for (int tm = 0; tm < 4; tm++) {
            uint32_t aa = sb + (uint32_t)rA[tm] * 512u
                        + (uint32_t)(((k0c + cAdd) ^ xA[tm]) << 4);
            ldsm4(ah[tm], aa + SA_HI);
            ldsm4(al[tm], aa + SA_LO);
        }
#pragma unroll
        for (int tm = 0; tm < 4; tm++) {
#pragma unroll
            for (int tn = 0; tn < 2; tn++) {
                mma_bf16(acc[tm][tn], ah[tm], &bh[2*tn]);   // hi*hi
                mma_bf16(acc[tm][tn], ah[tm], &bl[2*tn]);   // hi*lo
                mma_bf16(acc[tm][tn], al[tm], &bh[2*tn]);   // lo*hi
            }
        }
    }

    // ---- epilogue: bias + store ----
    const int row_in = lane >> 2;
    const int col_in = 2 * (lane & 3);
#pragma unroll
    for (int tn = 0; tn < 2; tn++) {
        const int gcol = col0 + wn * 16 + tn * 8 + col_in;
        const float bx = bias[gcol];
        const float by = bias[gcol + 1];
#pragma unroll
        for (int tm = 0; tm < 4; tm++) {
            const int gr = row0 + wm * 64 + tm * 16 + row_in;
            if (gr < M) {
                float2 o = make_float2(acc[tm][tn][0] + bx, acc[tm][tn][1] + by);
                *(float2*)&C[(size_t)gr * N + gcol] = o;
            }
            if (gr + 8 < M) {
                float2 o = make_float2(acc[tm][tn][2] + bx, acc[tm][tn][3] + by);
                *(float2*)&C[(size_t)(gr + 8) * N + gcol] = o;
            }
        }
    }
}

// ---------------------------------------------------------------------------
// Sampler (unchanged — gather-bound at 90.8us)
// ---------------------------------------------------------------------------
#define QPB 2

__global__ __launch_bounds__(256) void deform_sample(
    const float* __restrict__ ref_points, float* __restrict__ out)
{
    __shared__ float4 s_w[QPB * COMBOS];
    __shared__ int4   s_i[QPB * COMBOS];

    const int t = threadIdx.x;
    {
        const int q    = t >> 7;
        const int c    = t & 127;
        const int head = c >> 4;
        const int i16  = c & 15;
        const int lv   = i16 >> 2;
        const int bn   = blockIdx.x * QPB + q;
        const int b    = bn / NQ;

        float lg = g_attn[(size_t)bn * COMBOS + c];
        float mx = lg;
#pragma unroll
        for (int s = 8; s >= 1; s >>= 1)
            mx = fmaxf(mx, __shfl_xor_sync(0xffffffffu, mx, s));
        float e = __expf(lg - mx);
        float ssum = e;
#pragma unroll
        for (int s = 8; s >= 1; s >>= 1)
            ssum += __shfl_xor_sync(0xffffffffu, ssum, s);
        const float aw = e / ssum;

        const float2 od = ((const float2*)g_off)[(size_t)bn * COMBOS + c];
        const float rx = ref_points[bn * 2 + 0];
        const float ry = ref_points[bn * 2 + 1];

        const int   S  = c_shape[lv];
        const float fS = (float)S;
        const float x = (rx + od.x / fS) * fS - 0.5f;
        const float y = (ry + od.y / fS) * fS - 0.5f;
        const float x0f = floorf(x), y0f = floorf(y);
        const float lx = x - x0f, ly = y - y0f;
        const int x0 = (int)x0f, y0 = (int)y0f;
        const int x1 = x0 + 1,   y1 = y0 + 1;

        const bool vx0 = ((unsigned)x0 < (unsigned)S);
        const bool vx1 = ((unsigned)x1 < (unsigned)S);
        const bool vy0 = ((unsigned)y0 < (unsigned)S);
        const bool vy1 = ((unsigned)y1 < (unsigned)S);

        const int xc0 = min(max(x0, 0), S - 1);
        const int xc1 = min(max(x1, 0), S - 1);
        const int yc0 = min(max(y0, 0), S - 1);
        const int yc1 = min(max(y1, 0), S - 1);

        float4 wv;
        wv.x = (vx0 && vy0) ? (1.f - lx) * (1.f - ly) * aw : 0.f;
        wv.y = (vx1 && vy0) ? lx * (1.f - ly) * aw : 0.f;
        wv.z = (vx0 && vy1) ? (1.f - lx) * ly * aw : 0.f;
        wv.w = (vx1 && vy1) ? lx * ly * aw : 0.f;

        const int base = b * MTOT + c_start[lv];
        const int hoff = head * HEAD_DIM;
        int4 iv;
        iv.x = (base + yc0 * S + xc0) * EMBED + hoff;
        iv.y = (base + yc0 * S + xc1) * EMBED + hoff;
        iv.z = (base + yc1 * S + xc0) * EMBED + hoff;
        iv.w = (base + yc1 * S + xc1) * EMBED + hoff;

        s_w[t] = wv;
        s_i[t] = iv;
    }
    __syncthreads();

    const int head = t >> 5;
    const int lane = t & 31;
#pragma unroll
    for (int q = 0; q < QPB; q++) {
        const int bn   = blockIdx.x * QPB + q;
        const int slot = q * COMBOS + head * (LEVELS * POINTS);
        float acc = 0.0f;
#pragma unroll
        for (int i = 0; i < LEVELS * POINTS; i++) {
            const float4 wv = s_w[slot + i];
            const int4   iv = s_i[slot + i];
            float v0 = __ldg(&g_v[iv.x + lane]);
            float v1 = __ldg(&g_v[iv.y + lane]);
            float v2 = __ldg(&g_v[iv.z + lane]);
            float v3 = __ldg(&g_v[iv.w + lane]);
            acc = fmaf(wv.x, v0, acc);
            acc = fmaf(wv.y, v1, acc);
            acc = fmaf(wv.z, v2, acc);
            acc = fmaf(wv.w, v3, acc);
        }
        out[(size_t)bn * EMBED + head * HEAD_DIM + lane] = acc;
    }
}

// ---------------------------------------------------------------------------
// Launch
// ---------------------------------------------------------------------------
extern "C" void kernel_launch(void* const* d_in, const int* in_sizes, int n_in,
                              void* d_out, int out_size)
{
    const float* query  = (const float*)d_in[0];
    const float* value  = (const float*)d_in[2];
    const float* refpts = (const float*)d_in[3];
    const float* W_off  = (const float*)d_in[6];
    const float* b_off  = (const float*)d_in[7];
    const float* W_attn = (const float*)d_in[8];
    const float* b_attn = (const float*)d_in[9];
    const float* W_v    = (const float*)d_in[10];
    const float* b_v    = (const float*)d_in[11];
    float* out = (float*)d_out;

    void *pv, *poff, *pattn;
    void *pvh, *pvl, *pqh, *pql;
    void *pwvh, *pwvl, *pwoh, *pwol, *pwah, *pwal;
    cudaGetSymbolAddress(&pv, g_v);
    cudaGetSymbolAddress(&poff, g_off);
    cudaGetSymbolAddress(&pattn, g_attn);
    cudaGetSymbolAddress(&pvh, g_val_hi);  cudaGetSymbolAddress(&pvl, g_val_lo);
    cudaGetSymbolAddress(&pqh, g_q_hi);    cudaGetSymbolAddress(&pql, g_q_lo);
    cudaGetSymbolAddress(&pwvh, g_wv_hi);  cudaGetSymbolAddress(&pwvl, g_wv_lo);
    cudaGetSymbolAddress(&pwoh, g_wo_hi);  cudaGetSymbolAddress(&pwol, g_wo_lo);
    cudaGetSymbolAddress(&pwah, g_wa_hi);  cudaGetSymbolAddress(&pwal, g_wa_lo);

    const int MV = BATCH * MTOT;   // 43520
    const int MQ = BATCH * NQ;     // 20000

    cudaFuncSetAttribute(gemm_hmma, cudaFuncAttributeMaxDynamicSharedMemorySize, SM_TOTAL);

    // prep
    {
        int n4 = MV * KDIM / 4;
        split_rows<<<(n4 + 255) / 256, 256>>>(value, (__nv_bfloat16*)pvh, (__nv_bfloat16*)pvl, n4);
    }
    {
        int n4 = MQ * KDIM / 4;
        split_rows<<<(n4 + 255) / 256, 256>>>(query, (__nv_bfloat16*)pqh, (__nv_bfloat16*)pql, n4);
    }
    transpose_split<<<(256 * KDIM + 255) / 256, 256>>>(W_v,   (__nv_bfloat16*)pwvh, (__nv_bfloat16*)pwvl, 256);
    transpose_split<<<(256 * KDIM + 255) / 256, 256>>>(W_off, (__nv_bfloat16*)pwoh, (__nv_bfloat16*)pwol, 256);
    transpose_split<<<(128 * KDIM + 255) / 256, 256>>>(W_attn,(__nv_bfloat16*)pwah, (__nv_bfloat16*)pwal, 128);

    // HMMA GEMMs
    {
        dim3 grid(256 / 64, (MV + 127) / 128);
        gemm_hmma<<<grid, 256, SM_TOTAL>>>((const __nv_bfloat16*)pvh, (const __nv_bfloat16*)pvl,
                                           (const __nv_bfloat16*)pwvh, (const __nv_bfloat16*)pwvl,
                                           b_v, (float*)pv, MV, 256);
    }
    {
        dim3 grid(256 / 64, (MQ + 127) / 128);
        gemm_hmma<<<grid, 256, SM_TOTAL>>>((const __nv_bfloat16*)pqh, (const __nv_bfloat16*)pql,
                                           (const __nv_bfloat16*)pwoh, (const __nv_bfloat16*)pwol,
                                           b_off, (float*)poff, MQ, 256);
    }
    {
        dim3 grid(128 / 64, (MQ + 127) / 128);
        gemm_hmma<<<grid, 256, SM_TOTAL>>>((const __nv_bfloat16*)pqh, (const __nv_bfloat16*)pql,
                                           (const __nv_bfloat16*)pwah, (const __nv_bfloat16*)pwal,
                                           b_attn, (float*)pattn, MQ, 128);
    }

    // sampler
    deform_sample<<<(BATCH * NQ) / QPB, 256>>>(refpts, out);
}

// round 7
// speedup vs baseline: 2.6001x; 1.2506x over previous
#include <cuda_runtime.h>
#include <cuda_bf16.h>
#include <math.h>
#include <stdint.h>

// ---------------------------------------------------------------------------
// Problem constants
// ---------------------------------------------------------------------------
#define BATCH     2
#define NQ        10000
#define MTOT      21760
#define EMBED     256
#define HEADS     8
#define HEAD_DIM  32
#define LEVELS    4
#define POINTS    4
#define COMBOS    (HEADS*LEVELS*POINTS)
#define KDIM      256

__device__ __constant__ int c_shape[LEVELS]  = {128, 64, 32, 16};
__device__ __constant__ int c_start[LEVELS]  = {0, 16384, 20480, 21504};

// ---------------------------------------------------------------------------
// Device scratch
// ---------------------------------------------------------------------------
__device__ float g_v[BATCH * MTOT * EMBED];
__device__ float g_off[BATCH * NQ * (COMBOS*2)];
__device__ float g_attn[BATCH * NQ * COMBOS];

__device__ __nv_bfloat16 g_val_hi[BATCH * MTOT * KDIM];
__device__ __nv_bfloat16 g_val_lo[BATCH * MTOT * KDIM];
__device__ __nv_bfloat16 g_q_hi[BATCH * NQ * KDIM];
__device__ __nv_bfloat16 g_q_lo[BATCH * NQ * KDIM];
__device__ __nv_bfloat16 g_wv_hi[256 * KDIM],  g_wv_lo[256 * KDIM];
__device__ __nv_bfloat16 g_wo_hi[256 * KDIM],  g_wo_lo[256 * KDIM];
__device__ __nv_bfloat16 g_wa_hi[128 * KDIM],  g_wa_lo[128 * KDIM];

// ---------------------------------------------------------------------------
// PTX wrappers (baseline sm_80+ features; safe under plain sm_103 PTX target)
// ---------------------------------------------------------------------------
__device__ __forceinline__ uint32_t smem_u32(const void* p) {
    uint32_t a;
    asm("{ .reg .u64 t; cvta.to.shared.u64 t, %1; cvt.u32.u64 %0, t; }" : "=r"(a) : "l"(p));
    return a;
}
__device__ __forceinline__ void ldsm4(uint32_t* r, uint32_t addr) {
    asm volatile("ldmatrix.sync.aligned.m8n8.x4.shared.b16 {%0,%1,%2,%3}, [%4];"
        : "=r"(r[0]), "=r"(r[1]), "=r"(r[2]), "=r"(r[3]) : "r"(addr));
}
__device__ __forceinline__ void mma_bf16(float* c, const uint32_t* a, const uint32_t* b) {
    asm volatile("mma.sync.aligned.m16n8k16.row.col.f32.bf16.bf16.f32 "
        "{%0,%1,%2,%3}, {%4,%5,%6,%7}, {%8,%9}, {%0,%1,%2,%3};"
        : "+f"(c[0]), "+f"(c[1]), "+f"(c[2]), "+f"(c[3])
        : "r"(a[0]), "r"(a[1]), "r"(a[2]), "r"(a[3]), "r"(b[0]), "r"(b[1]));
}
__device__ __forceinline__ void cpa16(uint32_t dst, const void* src, uint32_t sz) {
    asm volatile("cp.async.ca.shared.global [%0], [%1], 16, %2;" :: "r"(dst), "l"(src), "r"(sz));
}
#define CPA_COMMIT()  asm volatile("cp.async.commit_group;" ::: "memory")
#define CPA_WAIT1()   asm volatile("cp.async.wait_group 1;" ::: "memory")
#define CPA_WAIT0()   asm volatile("cp.async.wait_group 0;" ::: "memory")

// ---------------------------------------------------------------------------
// Prep: fused fp32->bf16 hi/lo splits for value+query (one launch)
// ---------------------------------------------------------------------------
__device__ __forceinline__ void split4(const float* in, __nv_bfloat16* hi,
                                       __nv_bfloat16* lo, int i) {
    float4 a = ((const float4*)in)[i];
    __nv_bfloat16 h[4], l[4];
    float v[4] = {a.x, a.y, a.z, a.w};
#pragma unroll
    for (int j = 0; j < 4; j++) {
        h[j] = __float2bfloat16(v[j]);
        l[j] = __float2bfloat16(v[j] - __bfloat162float(h[j]));
    }
    ((uint2*)hi)[i] = *(uint2*)h;
    ((uint2*)lo)[i] = *(uint2*)l;
}

__global__ void split_all(const float* __restrict__ value, const float* __restrict__ query,
                          __nv_bfloat16* __restrict__ vh, __nv_bfloat16* __restrict__ vl,
                          __nv_bfloat16* __restrict__ qh, __nv_bfloat16* __restrict__ ql,
                          int nv4, int nq4)
{
    int i = blockIdx.x * blockDim.x + threadIdx.x;
    if (i < nv4)            split4(value, vh, vl, i);
    else if (i < nv4 + nq4) split4(query, qh, ql, i - nv4);
}

// Fused transpose+split of all three weight matrices (one launch).
__global__ void prep_weights(const float* __restrict__ Wv, const float* __restrict__ Wo,
                             const float* __restrict__ Wa,
                             __nv_bfloat16* __restrict__ vh, __nv_bfloat16* __restrict__ vl,
                             __nv_bfloat16* __restrict__ oh, __nv_bfloat16* __restrict__ ol,
                             __nv_bfloat16* __restrict__ ah, __nv_bfloat16* __restrict__ al)
{
    int idx = blockIdx.x * blockDim.x + threadIdx.x;   // 0 .. 163839
    const float* W; __nv_bfloat16 *hi, *lo; int Nin, local;
    if (idx < 65536)        { W = Wv; hi = vh; lo = vl; Nin = 256; local = idx; }
    else if (idx < 131072)  { W = Wo; hi = oh; lo = ol; Nin = 256; local = idx - 65536; }
    else if (idx < 163840)  { W = Wa; hi = ah; lo = al; Nin = 128; local = idx - 131072; }
    else return;
    int n = local >> 8;
    int k = local & 255;
    float v = W[k * Nin + n];
    __nv_bfloat16 h = __float2bfloat16(v);
    hi[local] = h;
    lo[local] = __float2bfloat16(v - __bfloat162float(h));
}

// ---------------------------------------------------------------------------
// HMMA GEMM v2:  C[M,N] = A[M,256] * Bt[N,256]^T + bias
// CTA tile 128x128, BK=64, cp.async double-buffered. 256 thr (8 warps, 4m x 2n).
// bf16 hi/lo 3-term split.
// smem/stage (64KB): [A_hi 16K][A_lo 16K][B_hi 16K][B_lo 16K]; 2 stages = 128KB.
// ---------------------------------------------------------------------------
#define STG   65536
#define OAL   16384
#define OBH   32768
#define OBL   49152
#define SM_TOTAL (2*STG)

__device__ __forceinline__ uint32_t sw128(int row, int ch) {   // row<128, ch<8 (16B chunks)
    return (uint32_t)row * 128u + (uint32_t)((ch ^ (row & 7)) << 4);
}

__global__ __launch_bounds__(256) void gemm_hmma2(
    const __nv_bfloat16* __restrict__ Ahi, const __nv_bfloat16* __restrict__ Alo,
    const __nv_bfloat16* __restrict__ Bhi, const __nv_bfloat16* __restrict__ Blo,
    const float* __restrict__ bias, float* __restrict__ C, int M, int N)
{
    extern __shared__ char smem[];
    const uint32_t sb = smem_u32(smem);
    const int tid  = threadIdx.x;
    const int wid  = tid >> 5;
    const int lane = tid & 31;
    const int wm   = wid & 3;        // 4 m-groups of 32 rows
    const int wn   = wid >> 2;       // 2 n-groups of 64 cols
    const int row0 = blockIdx.y * 128;
    const int col0 = blockIdx.x * 128;

    float acc[2][8][4];
#pragma unroll
    for (int a = 0; a < 2; a++)
#pragma unroll
        for (int b = 0; b < 8; b++)
#pragma unroll
            for (int f = 0; f < 4; f++) acc[a][b][f] = 0.f;

    // ---- async stage loader: 1024 16B-chunks per sub-tile, 4 per thread ----
#define LOAD_STAGE(stbase, k0)                                                  \
    do {                                                                        \
        _Pragma("unroll")                                                       \
        for (int i = 0; i < 4; i++) {                                           \
            int c   = tid + i * 256;                                            \
            int row = c >> 3;                                                   \
            int ch  = c & 7;                                                    \
            uint32_t sw = sw128(row, ch);                                       \
            int gr = row0 + row;                                                \
            uint32_t sz = (gr < M) ? 16u : 0u;                                  \
            size_t ga = (size_t)(gr < M ? gr : 0) * 256 + (k0) + ch * 8;        \
            cpa16(sb + (stbase) + sw,        Ahi + ga, sz);                     \
            cpa16(sb + (stbase) + OAL + sw,  Alo + ga, sz);                     \
            size_t gb = (size_t)(col0 + row) * 256 + (k0) + ch * 8;             \
            cpa16(sb + (stbase) + OBH + sw,  Bhi + gb, 16u);                    \
            cpa16(sb + (stbase) + OBL + sw,  Blo + gb, 16u);                    \
        }                                                                       \
    } while (0)

    LOAD_STAGE(0, 0);
    CPA_COMMIT();

#pragma unroll
    for (int cc = 0; cc < 4; cc++) {
        const uint32_t st = (uint32_t)(cc & 1) * STG;
        if (cc < 3) {
            LOAD_STAGE((uint32_t)((cc + 1) & 1) * STG, (cc + 1) * 64);
            CPA_COMMIT();
            CPA_WAIT1();
        } else {
            CPA_WAIT0();
        }
        __syncthreads();

        // ---- compute this 64-wide K chunk: 4 k16-steps ----
#pragma unroll
        for (int ks = 0; ks < 4; ks++) {
            uint32_t ah[2][4], al[2][4];
#pragma unroll
            for (int tm = 0; tm < 2; tm++) {
                int rA = wm * 32 + tm * 16 + (lane & 15);
                int ch = 2 * ks + (lane >> 4);
                uint32_t ad = sb + st + sw128(rA, ch);
                ldsm4(ah[tm], ad);
                ldsm4(al[tm], ad + OAL);
            }
#pragma unroll
            for (int g = 0; g < 4; g++) {
                int rB  = wn * 64 + g * 16 + ((lane >> 4) & 1) * 8 + (lane & 7);
                int chb = 2 * ks + ((lane >> 3) & 1);
                uint32_t bd = sb + st + OBH + sw128(rB, chb);
                uint32_t bh[4], bl[4];
                ldsm4(bh, bd);
                ldsm4(bl, bd + (OBL - OBH));
#pragma unroll
                for (int tm = 0; tm < 2; tm++) {
                    mma_bf16(acc[tm][2*g],   ah[tm], bh);       // hi*hi
                    mma_bf16(acc[tm][2*g],   ah[tm], bl);       // hi*lo
                    mma_bf16(acc[tm][2*g],   al[tm], bh);       // lo*hi
                    mma_bf16(acc[tm][2*g+1], ah[tm], bh + 2);
                    mma_bf16(acc[tm][2*g+1], ah[tm], bl + 2);
                    mma_bf16(acc[tm][2*g+1], al[tm], bh + 2);
                }
            }
        }
        __syncthreads();
    }

    // ---- epilogue: bias + store ----
    const int row_in = lane >> 2;
    const int col_in = 2 * (lane & 3);
#pragma unroll
    for (int tm = 0; tm < 2; tm++) {
        const int gr0 = row0 + wm * 32 + tm * 16 + row_in;
#pragma unroll
        for (int j = 0; j < 8; j++) {
            const int gcol = col0 + wn * 64 + j * 8 + col_in;
            const float bx = bias[gcol];
            const float by = bias[gcol + 1];
            if (gr0 < M) {
                float2 o = make_float2(acc[tm][j][0] + bx, acc[tm][j][1] + by);
                *(float2*)&C[(size_t)gr0 * N + gcol] = o;
            }
            if (gr0 + 8 < M) {
                float2 o = make_float2(acc[tm][j][2] + bx, acc[tm][j][3] + by);
                *(float2*)&C[(size_t)(gr0 + 8) * N + gcol] = o;
            }
        }
    }
#undef LOAD_STAGE
}

// ---------------------------------------------------------------------------
// Sampler (unchanged — gather-bound at ~91us)
// ---------------------------------------------------------------------------
#define QPB 2

__global__ __launch_bounds__(256) void deform_sample(
    const float* __restrict__ ref_points, float* __restrict__ out)
{
    __shared__ float4 s_w[QPB * COMBOS];
    __shared__ int4   s_i[QPB * COMBOS];

    const int t = threadIdx.x;
    {
        const int q    = t >> 7;
        const int c    = t & 127;
        const int head = c >> 4;
        const int i16  = c & 15;
        const int lv   = i16 >> 2;
        const int bn   = blockIdx.x * QPB + q;
        const int b    = bn / NQ;

        float lg = g_attn[(size_t)bn * COMBOS + c];
        float mx = lg;
#pragma unroll
        for (int s = 8; s >= 1; s >>= 1)
            mx = fmaxf(mx, __shfl_xor_sync(0xffffffffu, mx, s));
        float e = __expf(lg - mx);
        float ssum = e;
#pragma unroll
        for (int s = 8; s >= 1; s >>= 1)
            ssum += __shfl_xor_sync(0xffffffffu, ssum, s);
        const float aw = e / ssum;

        const float2 od = ((const float2*)g_off)[(size_t)bn * COMBOS + c];
        const float rx = ref_points[bn * 2 + 0];
        const float ry = ref_points[bn * 2 + 1];

        const int   S  = c_shape[lv];
        const float fS = (float)S;
        const float x = (rx + od.x / fS) * fS - 0.5f;
        const float y = (ry + od.y / fS) * fS - 0.5f;
        const float x0f = floorf(x), y0f = floorf(y);
        const float lx = x - x0f, ly = y - y0f;
        const int x0 = (int)x0f, y0 = (int)y0f;
        const int x1 = x0 + 1,   y1 = y0 + 1;

        const bool vx0 = ((unsigned)x0 < (unsigned)S);
        const bool vx1 = ((unsigned)x1 < (unsigned)S);
        const bool vy0 = ((unsigned)y0 < (unsigned)S);
        const bool vy1 = ((unsigned)y1 < (unsigned)S);

        const int xc0 = min(max(x0, 0), S - 1);
        const int xc1 = min(max(x1, 0), S - 1);
        const int yc0 = min(max(y0, 0), S - 1);
        const int yc1 = min(max(y1, 0), S - 1);

        float4 wv;
        wv.x = (vx0 && vy0) ? (1.f - lx) * (1.f - ly) * aw : 0.f;
        wv.y = (vx1 && vy0) ? lx * (1.f - ly) * aw : 0.f;
        wv.z = (vx0 && vy1) ? (1.f - lx) * ly * aw : 0.f;
        wv.w = (vx1 && vy1) ? lx * ly * aw : 0.f;

        const int base = b * MTOT + c_start[lv];
        const int hoff = head * HEAD_DIM;
        int4 iv;
        iv.x = (base + yc0 * S + xc0) * EMBED + hoff;
        iv.y = (base + yc0 * S + xc1) * EMBED + hoff;
        iv.z = (base + yc1 * S + xc0) * EMBED + hoff;
        iv.w = (base + yc1 * S + xc1) * EMBED + hoff;

        s_w[t] = wv;
        s_i[t] = iv;
    }
    __syncthreads();

    const int head = t >> 5;
    const int lane = t & 31;
#pragma unroll
    for (int q = 0; q < QPB; q++) {
        const int bn   = blockIdx.x * QPB + q;
        const int slot = q * COMBOS + head * (LEVELS * POINTS);
        float acc = 0.0f;
#pragma unroll
        for (int i = 0; i < LEVELS * POINTS; i++) {
            const float4 wv = s_w[slot + i];
            const int4   iv = s_i[slot + i];
            float v0 = __ldg(&g_v[iv.x + lane]);
            float v1 = __ldg(&g_v[iv.y + lane]);
            float v2 = __ldg(&g_v[iv.z + lane]);
            float v3 = __ldg(&g_v[iv.w + lane]);
            acc = fmaf(wv.x, v0, acc);
            acc = fmaf(wv.y, v1, acc);
            acc = fmaf(wv.z, v2, acc);
            acc = fmaf(wv.w, v3, acc);
        }
        out[(size_t)bn * EMBED + head * HEAD_DIM + lane] = acc;
    }
}

// ---------------------------------------------------------------------------
// Launch
// ---------------------------------------------------------------------------
extern "C" void kernel_launch(void* const* d_in, const int* in_sizes, int n_in,
                              void* d_out, int out_size)
{
    const float* query  = (const float*)d_in[0];
    const float* value  = (const float*)d_in[2];
    const float* refpts = (const float*)d_in[3];
    const float* W_off  = (const float*)d_in[6];
    const float* b_off  = (const float*)d_in[7];
    const float* W_attn = (const float*)d_in[8];
    const float* b_attn = (const float*)d_in[9];
    const float* W_v    = (const float*)d_in[10];
    const float* b_v    = (const float*)d_in[11];
    float* out = (float*)d_out;

    void *pv, *poff, *pattn;
    void *pvh, *pvl, *pqh, *pql;
    void *pwvh, *pwvl, *pwoh, *pwol, *pwah, *pwal;
    cudaGetSymbolAddress(&pv, g_v);
    cudaGetSymbolAddress(&poff, g_off);
    cudaGetSymbolAddress(&pattn, g_attn);
    cudaGetSymbolAddress(&pvh, g_val_hi);  cudaGetSymbolAddress(&pvl, g_val_lo);
    cudaGetSymbolAddress(&pqh, g_q_hi);    cudaGetSymbolAddress(&pql, g_q_lo);
    cudaGetSymbolAddress(&pwvh, g_wv_hi);  cudaGetSymbolAddress(&pwvl, g_wv_lo);
    cudaGetSymbolAddress(&pwoh, g_wo_hi);  cudaGetSymbolAddress(&pwol, g_wo_lo);
    cudaGetSymbolAddress(&pwah, g_wa_hi);  cudaGetSymbolAddress(&pwal, g_wa_lo);

    const int MV = BATCH * MTOT;   // 43520
    const int MQ = BATCH * NQ;     // 20000

    cudaFuncSetAttribute(gemm_hmma2, cudaFuncAttributeMaxDynamicSharedMemorySize, SM_TOTAL);

    // prep (2 launches)
    {
        int nv4 = MV * KDIM / 4, nq4 = MQ * KDIM / 4;
        int tot = nv4 + nq4;
        split_all<<<(tot + 255) / 256, 256>>>(value, query,
            (__nv_bfloat16*)pvh, (__nv_bfloat16*)pvl,
            (__nv_bfloat16*)pqh, (__nv_bfloat16*)pql, nv4, nq4);
    }
    prep_weights<<<(163840 + 255) / 256, 256>>>(W_v, W_off, W_attn,
        (__nv_bfloat16*)pwvh, (__nv_bfloat16*)pwvl,
        (__nv_bfloat16*)pwoh, (__nv_bfloat16*)pwol,
        (__nv_bfloat16*)pwah, (__nv_bfloat16*)pwal);

    // GEMMs
    {
        dim3 grid(2, (MV + 127) / 128);   // N=256
        gemm_hmma2<<<grid, 256, SM_TOTAL>>>((const __nv_bfloat16*)pvh, (const __nv_bfloat16*)pvl,
                                            (const __nv_bfloat16*)pwvh, (const __nv_bfloat16*)pwvl,
                                            b_v, (float*)pv, MV, 256);
    }
    {
        dim3 grid(2, (MQ + 127) / 128);   // N=256
        gemm_hmma2<<<grid, 256, SM_TOTAL>>>((const __nv_bfloat16*)pqh, (const __nv_bfloat16*)pql,
                                            (const __nv_bfloat16*)pwoh, (const __nv_bfloat16*)pwol,
                                            b_off, (float*)poff, MQ, 256);
    }
    {
        dim3 grid(1, (MQ + 127) / 128);   // N=128
        gemm_hmma2<<<grid, 256, SM_TOTAL>>>((const __nv_bfloat16*)pqh, (const __nv_bfloat16*)pql,
                                            (const __nv_bfloat16*)pwah, (const __nv_bfloat16*)pwal,
                                            b_attn, (float*)pattn, MQ, 128);
    }

    // sampler
    deform_sample<<<(BATCH * NQ) / QPB, 256>>>(refpts, out);
}